// round 7
// baseline (speedup 1.0000x reference)
#include <cuda_runtime.h>

#define NN 50000
#define EE 800000
#define FDIM 128
#define NBLK 49  // ceil(NN/1024)

typedef unsigned long long ull;

// ---------------- scratch (device globals; no allocation) ----------------
__device__ float g_xl[NN * FDIM];
__device__ float g_xr[NN * FDIM];
__device__ float g_h[NN * FDIM];
__device__ int g_counts[NN];
__device__ int g_rowptr[NN + 1];
__device__ int g_next[NN];
__device__ int g_src[EE];
__device__ int g_is64;
__device__ int g_blksum[64];
__device__ int g_blkoff[64];

// ---------------- side stream + fork/join events (static init: before harness checkpoints) ----------------
struct SideStream {
    cudaStream_t s2;
    cudaEvent_t e1, e2;
    SideStream() {
        cudaStreamCreateWithFlags(&s2, cudaStreamNonBlocking);
        cudaEventCreateWithFlags(&e1, cudaEventDisableTiming);
        cudaEventCreateWithFlags(&e2, cudaEventDisableTiming);
    }
};
static SideStream g_ss;

// ---------------- f32x2 packed-FMA helper (SASS FFMA2; PTX-only path) ----------------
__device__ __forceinline__ void fma2(ull& d, ull a, ull b) {
    asm("fma.rn.f32x2 %0, %1, %2, %0;" : "+l"(d) : "l"(a), "l"(b));
}
__device__ __forceinline__ float2 unpack2(ull v) {
    float2 f;
    asm("mov.b64 {%0, %1}, %2;" : "=f"(f.x), "=f"(f.y) : "l"(v));
    return f;
}

// ---------------- detect dtype (int32 vs int64) + zero counts, one launch ----------------
__global__ void k_detect_zero(const unsigned int* __restrict__ w) {
    int i = blockIdx.x * 256 + threadIdx.x;
    if (i < NN) g_counts[i] = 0;
    if (blockIdx.x == 0) {
        __shared__ int cnt;
        if (threadIdx.x == 0) cnt = 0;
        __syncthreads();
        int z = 0;
        for (int k = threadIdx.x; k < 1024; k += 256)
            if (w[2 * k + 1] == 0u) z++;
        atomicAdd(&cnt, z);
        __syncthreads();
        if (threadIdx.x == 0) g_is64 = (cnt > 512) ? 1 : 0;
    }
}

__device__ __forceinline__ int load_idx(const void* ei, long pos) {
    return g_is64 ? (int)((const long long*)ei)[pos] : ((const int*)ei)[pos];
}

// ---------------- CSR build ----------------
__global__ void k_hist(const void* __restrict__ ei) {
    int e = blockIdx.x * blockDim.x + threadIdx.x;
    if (e < EE) atomicAdd(&g_counts[load_idx(ei, (long)EE + e)], 1);
}

__global__ void k_scan_block() {
    __shared__ int wsum[32];
    int i = blockIdx.x * 1024 + threadIdx.x;
    int lane = threadIdx.x & 31, wid = threadIdx.x >> 5;
    int v = (i < NN) ? g_counts[i] : 0;
    int incl = v;
#pragma unroll
    for (int o = 1; o < 32; o <<= 1) {
        int xx = __shfl_up_sync(0xffffffffu, incl, o);
        if (lane >= o) incl += xx;
    }
    if (lane == 31) wsum[wid] = incl;
    __syncthreads();
    if (wid == 0) {
        int ws = wsum[lane];
        int wincl = ws;
#pragma unroll
        for (int o = 1; o < 32; o <<= 1) {
            int xx = __shfl_up_sync(0xffffffffu, wincl, o);
            if (lane >= o) wincl += xx;
        }
        wsum[lane] = wincl - ws;
    }
    __syncthreads();
    int excl = wsum[wid] + incl - v;
    if (i < NN) g_rowptr[i] = excl;
    if (threadIdx.x == 1023) g_blksum[blockIdx.x] = excl + v;
}

__global__ void k_scan_tops() {
    int lane = threadIdx.x;
    int v0 = (2 * lane < NBLK) ? g_blksum[2 * lane] : 0;
    int v1 = (2 * lane + 1 < NBLK) ? g_blksum[2 * lane + 1] : 0;
    int s = v0 + v1;
    int incl = s;
#pragma unroll
    for (int o = 1; o < 32; o <<= 1) {
        int xx = __shfl_up_sync(0xffffffffu, incl, o);
        if (lane >= o) incl += xx;
    }
    int excl = incl - s;
    if (2 * lane < NBLK) g_blkoff[2 * lane] = excl;
    if (2 * lane + 1 < NBLK) g_blkoff[2 * lane + 1] = excl + v0;
    if (lane == 31) g_rowptr[NN] = incl;
}

__global__ void k_scan_add() {
    int i = blockIdx.x * 1024 + threadIdx.x;
    if (i < NN) {
        int r = g_rowptr[i] + g_blkoff[blockIdx.x];
        g_rowptr[i] = r;
        g_next[i] = r;
    }
}

__global__ void k_scatter(const void* __restrict__ ei) {
    int e = blockIdx.x * blockDim.x + threadIdx.x;
    if (e < EE) {
        int dn = load_idx(ei, (long)EE + e);
        int sn = load_idx(ei, e);
        int pos = atomicAdd(&g_next[dn], 1);
        g_src[pos] = sn;
    }
}

// ---------------- dual GEMM: g_xl = A@W1, g_xr = A@W2  (M=NN, K=N=128) ----------------
// 128x256 block tile, 512 threads, 8x8 micro-tile via f32x2 packed FMA.
// A stored DUPLICATED in smem so the broadcast FFMA2 operand needs zero pack MOVs.
template <bool USE_H>
__global__ void __launch_bounds__(512, 1)
k_dual_gemm(const float* __restrict__ A_param,
            const float* __restrict__ W1, const float* __restrict__ W2) {
    const float* A = USE_H ? (const float*)g_h : A_param;
    __shared__ float As2[16][256];  // As2[k][2r]=As2[k][2r+1]=A[row0+r][kc+k]
    __shared__ float Ws[16][256];   // Ws[k][col] (W1 | W2)
    int t = threadIdx.x;
    int row0 = blockIdx.x * 128;
    int rt = t >> 5, ct = t & 31;   // rt warp-uniform -> As2 reads broadcast
    int ar = t >> 2, ac = t & 3;    // A-load coords: row 0..127, k-group 0..3
    int gr = row0 + ar;

    ull acc2[8][4];
#pragma unroll
    for (int i = 0; i < 8; i++)
#pragma unroll
        for (int j = 0; j < 4; j++) acc2[i][j] = 0ull;

    float4 aT, wT[2];
    // prologue load: chunk kc=0
    aT = (gr < NN) ? *(const float4*)(A + (long)gr * FDIM + ac * 4)
                   : make_float4(0.f, 0.f, 0.f, 0.f);
#pragma unroll
    for (int i = 0; i < 2; i++) {
        int idx = t + i * 512;
        int k = idx >> 6, c4 = idx & 63;
        wT[i] = (c4 < 32) ? *(const float4*)(W1 + k * FDIM + c4 * 4)
                          : *(const float4*)(W2 + k * FDIM + (c4 - 32) * 4);
    }

    for (int kc = 0; kc < 128; kc += 16) {
        // store staged chunk: A duplicated
        float av[4] = {aT.x, aT.y, aT.z, aT.w};
#pragma unroll
        for (int i = 0; i < 4; i++)
            *(float2*)(&As2[ac * 4 + i][2 * ar]) = make_float2(av[i], av[i]);
#pragma unroll
        for (int i = 0; i < 2; i++) {
            int idx = t + i * 512;
            int k = idx >> 6, c4 = idx & 63;
            *(float4*)(&Ws[k][c4 * 4]) = wT[i];
        }
        __syncthreads();

        // prefetch next chunk while computing
        int kn = kc + 16;
        if (kn < 128) {
            aT = (gr < NN) ? *(const float4*)(A + (long)gr * FDIM + kn + ac * 4)
                           : make_float4(0.f, 0.f, 0.f, 0.f);
#pragma unroll
            for (int i = 0; i < 2; i++) {
                int idx = t + i * 512;
                int k = idx >> 6, c4 = idx & 63;
                wT[i] = (c4 < 32) ? *(const float4*)(W1 + (kn + k) * FDIM + c4 * 4)
                                  : *(const float4*)(W2 + (kn + k) * FDIM + (c4 - 32) * 4);
            }
        }

#pragma unroll 8
        for (int kk = 0; kk < 16; kk++) {
            // packed duplicated A rows straight from broadcast LDS.128
            ulonglong2 aD0 = *(const ulonglong2*)(&As2[kk][rt * 16]);
            ulonglong2 aD1 = *(const ulonglong2*)(&As2[kk][rt * 16 + 4]);
            ulonglong2 aD2 = *(const ulonglong2*)(&As2[kk][rt * 16 + 8]);
            ulonglong2 aD3 = *(const ulonglong2*)(&As2[kk][rt * 16 + 12]);
            ulonglong2 w01 = *(const ulonglong2*)(&Ws[kk][ct * 4]);
            ulonglong2 w23 = *(const ulonglong2*)(&Ws[kk][ct * 4 + 128]);
            ull ad[8] = {aD0.x, aD0.y, aD1.x, aD1.y, aD2.x, aD2.y, aD3.x, aD3.y};
#pragma unroll
            for (int i = 0; i < 8; i++) {
                fma2(acc2[i][0], ad[i], w01.x);
                fma2(acc2[i][1], ad[i], w01.y);
                fma2(acc2[i][2], ad[i], w23.x);
                fma2(acc2[i][3], ad[i], w23.y);
            }
        }
        __syncthreads();
    }

#pragma unroll
    for (int i = 0; i < 8; i++) {
        int gr2 = row0 + rt * 8 + i;
        if (gr2 < NN) {
            float2 p0 = unpack2(acc2[i][0]), p1 = unpack2(acc2[i][1]);
            float2 p2 = unpack2(acc2[i][2]), p3 = unpack2(acc2[i][3]);
            *(float4*)(g_xl + (long)gr2 * FDIM + ct * 4) =
                make_float4(p0.x, p0.y, p1.x, p1.y);
            *(float4*)(g_xr + (long)gr2 * FDIM + ct * 4) =
                make_float4(p2.x, p2.y, p3.x, p3.y);
        }
    }
}

// ---------------- fused per-node attention (online softmax), warp per node ----------------
__device__ __forceinline__ float lrelu(float v) { return v > 0.f ? v : 0.2f * v; }

template <int H, bool OUT_H>
__global__ void k_aggregate(const float* __restrict__ att, const float* __restrict__ bias,
                            float* __restrict__ out_param) {
    float* out = OUT_H ? (float*)g_h : out_param;
    int gw = (blockIdx.x * blockDim.x + threadIdx.x) >> 5;
    int lane = threadIdx.x & 31;
    if (gw >= NN) return;
    int n = gw;

    float4 xrv = *(const float4*)(g_xr + (long)n * FDIM + lane * 4);
    float4 av  = *(const float4*)(att + lane * 4);
    float4 bv  = *(const float4*)(bias + lane * 4);

    // self-loop first: bootstraps m/d/acc, no -inf handling
    float4 xlv = *(const float4*)(g_xl + (long)n * FDIM + lane * 4);
    float p = lrelu(xlv.x + xrv.x) * av.x
            + lrelu(xlv.y + xrv.y) * av.y
            + lrelu(xlv.z + xrv.z) * av.z
            + lrelu(xlv.w + xrv.w) * av.w;
#pragma unroll
    for (int o = 1; o < 32 / H; o <<= 1)
        p += __shfl_xor_sync(0xffffffffu, p, o);
    float m = p;
    float d = 1.f;
    float4 acc = xlv;

    int start = g_rowptr[n], end = g_rowptr[n + 1];
    for (int j = start; j < end; j++) {
        int s = g_src[j];
        xlv = *(const float4*)(g_xl + (long)s * FDIM + lane * 4);
        p = lrelu(xlv.x + xrv.x) * av.x
          + lrelu(xlv.y + xrv.y) * av.y
          + lrelu(xlv.z + xrv.z) * av.z
          + lrelu(xlv.w + xrv.w) * av.w;
#pragma unroll
        for (int o = 1; o < 32 / H; o <<= 1)
            p += __shfl_xor_sync(0xffffffffu, p, o);
        if (p > m) {
            float sc = __expf(m - p);
            d = fmaf(d, sc, 1.f);
            acc.x = fmaf(acc.x, sc, xlv.x);
            acc.y = fmaf(acc.y, sc, xlv.y);
            acc.z = fmaf(acc.z, sc, xlv.z);
            acc.w = fmaf(acc.w, sc, xlv.w);
            m = p;
        } else {
            float pe = __expf(p - m);
            d += pe;
            acc.x = fmaf(pe, xlv.x, acc.x);
            acc.y = fmaf(pe, xlv.y, acc.y);
            acc.z = fmaf(pe, xlv.z, acc.z);
            acc.w = fmaf(pe, xlv.w, acc.w);
        }
    }
    float inv = 1.f / d;
    float4 o = make_float4(fmaf(acc.x, inv, bv.x), fmaf(acc.y, inv, bv.y),
                           fmaf(acc.z, inv, bv.z), fmaf(acc.w, inv, bv.w));
    *(float4*)(out + (long)n * FDIM + lane * 4) = o;
}

// ---------------- launch ----------------
extern "C" void kernel_launch(void* const* d_in, const int* in_sizes, int n_in,
                              void* d_out, int out_size) {
    const float* x    = (const float*)d_in[0];
    const void*  ei   = d_in[1];
    const float* Wl1  = (const float*)d_in[3];
    const float* Wr1  = (const float*)d_in[4];
    const float* att1 = (const float*)d_in[5];
    const float* b1   = (const float*)d_in[6];
    const float* Wl2  = (const float*)d_in[7];
    const float* Wr2  = (const float*)d_in[8];
    const float* att2 = (const float*)d_in[9];
    const float* b2   = (const float*)d_in[10];
    float* out = (float*)d_out;

    int gemm_blocks = (NN + 127) / 128;
    int agg_blocks = (NN + 7) / 8;
    cudaStream_t s2 = g_ss.s2;

    // fork: CSR build on s2, concurrent with layer-1 GEMM on main stream
    cudaEventRecord(g_ss.e1, 0);
    cudaStreamWaitEvent(s2, g_ss.e1, 0);

    k_detect_zero<<<(NN + 255) / 256, 256, 0, s2>>>((const unsigned int*)ei);
    k_hist<<<(EE + 255) / 256, 256, 0, s2>>>(ei);
    k_scan_block<<<NBLK, 1024, 0, s2>>>();
    k_scan_tops<<<1, 32, 0, s2>>>();
    k_scan_add<<<NBLK, 1024, 0, s2>>>();
    k_scatter<<<(EE + 255) / 256, 256, 0, s2>>>(ei);
    cudaEventRecord(g_ss.e2, s2);

    k_dual_gemm<false><<<gemm_blocks, 512>>>(x, Wl1, Wr1);  // concurrent with CSR

    // join
    cudaStreamWaitEvent(0, g_ss.e2, 0);

    k_aggregate<2, true><<<agg_blocks, 256>>>(att1, b1, nullptr);
    k_dual_gemm<true><<<gemm_blocks, 512>>>(nullptr, Wl2, Wr2);
    k_aggregate<1, false><<<agg_blocks, 256>>>(att2, b2, out);
}